// round 10
// baseline (speedup 1.0000x reference)
#include <cuda_runtime.h>
#include <math.h>
#include <stdint.h>

#define NUM_USERS 162541
#define NUM_ITEMS 59047
#define N_NODES   221588
#define DIM       128
#define N_EDGES   100000
#define BATCH     16384
#define MAXL1     132768    // |need1| <= 32768 + 100000
#define MAXL2     32768     // |need2| <= 32768

// ---------------- scratch (device globals; device-code use ONLY) ------------
// Invariant: masks/degrees/counters are ZERO on entry to every kernel_launch
// call (zero-init at load; each call cleans exactly what it dirtied).
__device__ float g_big[(size_t)N_NODES * 512];   // L1: aggH[n][h][128]; L2: agg2[n][128]
__device__ float g_h1 [(size_t)N_NODES * DIM];   // h1; later h2
__device__ unsigned char g_need1[N_NODES], g_need2[N_NODES];
__device__ int g_list1[MAXL1], g_list2[MAXL2];
__device__ int g_cnt1, g_cnt2, g_tot1, g_tot2;
__device__ int g_deg1[N_NODES], g_deg2[N_NODES];
__device__ int g_base1[N_NODES], g_base2[N_NODES];
__device__ int g_fc1[N_NODES], g_fc2[N_NODES];
__device__ int g_csr1[N_EDGES], g_csr2[N_EDGES];
__device__ float g_ws1[4 * DIM], g_wd1[4 * DIM];
__device__ float g_ws2[DIM],     g_wd2[DIM];

// ---------------- helpers ---------------------------------------------------
__device__ __forceinline__ float eluf(float x)  { return x > 0.f ? x : expm1f(x); }
__device__ __forceinline__ float lrelu(float x) { return x > 0.f ? x : 0.2f * x; }
__device__ __forceinline__ float wsum(float v) {
    #pragma unroll
    for (int o = 16; o; o >>= 1) v += __shfl_xor_sync(0xffffffffu, v, o);
    return v;
}
__device__ __forceinline__ const float* xrow(int n, const float* uT, const float* iT) {
    return (n < NUM_USERS) ? uT + (size_t)n * DIM
                           : iT + (size_t)(n - NUM_USERS) * DIM;
}
// packed dual-fp32 FMA (Blackwell f32x2 pipe; ptxas never auto-fuses this)
__device__ __forceinline__ void ffma2(unsigned long long& d,
                                      unsigned long long a, unsigned long long b) {
    asm("fma.rn.f32x2 %0, %1, %2, %0;" : "+l"(d) : "l"(a), "l"(b));
}
__device__ __forceinline__ unsigned long long bcast2(float x) {
    unsigned long long r; unsigned u = __float_as_uint(x);
    asm("mov.b64 %0, {%1, %1};" : "=l"(r) : "r"(u));
    return r;
}
__device__ __forceinline__ float lo2(unsigned long long v) {
    unsigned a, b; asm("mov.b64 {%0, %1}, %2;" : "=r"(a), "=r"(b) : "l"(v));
    return __uint_as_float(a);
}
__device__ __forceinline__ float hi2(unsigned long long v) {
    unsigned a, b; asm("mov.b64 {%0, %1}, %2;" : "=r"(a), "=r"(b) : "l"(v));
    return __uint_as_float(b);
}

// ---------------- 1: prep (fold W@att, reset counters) + batch marks --------
__global__ __launch_bounds__(256)
void prep_k(const float* __restrict__ W1, const float* __restrict__ aS1,
            const float* __restrict__ aD1, const float* __restrict__ W2,
            const float* __restrict__ aS2, const float* __restrict__ aD2,
            const int* __restrict__ uidx, const int* __restrict__ iidx)
{
    if (blockIdx.x == 0) {
        int k = threadIdx.x;
        if (k == 255) { g_cnt1 = 0; g_cnt2 = 0; g_tot1 = 0; g_tot2 = 0; }
        if (k < 128) {
            #pragma unroll
            for (int h = 0; h < 4; h++) {
                float s = 0.f, d = 0.f;
                #pragma unroll
                for (int c = 0; c < 32; c++) {
                    float w = W1[k * DIM + h * 32 + c];
                    s = fmaf(w, aS1[h * 32 + c], s);
                    d = fmaf(w, aD1[h * 32 + c], d);
                }
                g_ws1[h * DIM + k] = s;
                g_wd1[h * DIM + k] = d;
            }
            float s2 = 0.f, d2 = 0.f;
            for (int j = 0; j < DIM; j++) {
                float w = W2[k * DIM + j];
                s2 = fmaf(w, aS2[j], s2);
                d2 = fmaf(w, aD2[j], d2);
            }
            g_ws2[k] = s2;
            g_wd2[k] = d2;
        }
    } else {
        int i = (blockIdx.x - 1) * 256 + threadIdx.x;
        if (i < BATCH) {
            int u = uidx[i], v = iidx[i] + NUM_USERS;
            g_need2[u] = 1; g_need1[u] = 1;
            g_need2[v] = 1; g_need1[v] = 1;
        }
    }
}

// ---------------- 2: need1 |= srcs of edges into need2 ----------------------
__global__ void mark1_k(const int* __restrict__ ei)
{
    int e = blockIdx.x * blockDim.x + threadIdx.x;
    if (e >= N_EDGES) return;
    if (g_need2[ei[N_EDGES + e]]) g_need1[ei[e]] = 1;
}

// ---------------- 3: degree histograms ---------------------------------------
__global__ void markC_k(const int* __restrict__ ei)
{
    int e = blockIdx.x * blockDim.x + threadIdx.x;
    if (e >= N_EDGES) return;
    int d = ei[N_EDGES + e];
    if (g_need1[d]) atomicAdd(&g_deg1[d], 1);
    if (g_need2[d]) atomicAdd(&g_deg2[d], 1);
}

// ---------------- 4: list compaction + CSR base allocation (fused) ----------
__global__ __launch_bounds__(256)
void compactalloc_k()
{
    __shared__ int w1[8], w2[8];
    __shared__ int base1, base2;
    int i = blockIdx.x * 256 + threadIdx.x;
    int w = threadIdx.x >> 5, lane = threadIdx.x & 31;
    bool in1 = (i < N_NODES) && g_need1[i];
    bool in2 = (i < N_NODES) && g_need2[i];
    unsigned m1 = __ballot_sync(~0u, in1);
    unsigned m2 = __ballot_sync(~0u, in2);
    if (lane == 0) { w1[w] = __popc(m1); w2[w] = __popc(m2); }
    __syncthreads();
    if (threadIdx.x == 0) {
        int t1 = 0, t2 = 0;
        #pragma unroll
        for (int k = 0; k < 8; k++) {
            int v1 = w1[k]; w1[k] = t1; t1 += v1;
            int v2 = w2[k]; w2[k] = t2; t2 += v2;
        }
        base1 = (t1 > 0) ? atomicAdd(&g_cnt1, t1) : 0;
        base2 = (t2 > 0) ? atomicAdd(&g_cnt2, t2) : 0;
    }
    __syncthreads();
    unsigned lm = (1u << lane) - 1u;
    if (in1) g_list1[base1 + w1[w] + __popc(m1 & lm)] = i;
    if (in2) g_list2[base2 + w2[w] + __popc(m2 & lm)] = i;
    // CSR base ranges: warp-aggregated prefix over degrees (order-free)
    {
        int deg = in1 ? g_deg1[i] : 0;
        int inc = deg;
        #pragma unroll
        for (int o = 1; o < 32; o <<= 1) {
            int t = __shfl_up_sync(~0u, inc, o);
            if (lane >= o) inc += t;
        }
        int tot = __shfl_sync(~0u, inc, 31);
        int wb = 0;
        if (lane == 31 && tot > 0) wb = atomicAdd(&g_tot1, tot);
        wb = __shfl_sync(~0u, wb, 31);
        if (in1) g_base1[i] = wb + inc - deg;
    }
    {
        int deg = in2 ? g_deg2[i] : 0;
        int inc = deg;
        #pragma unroll
        for (int o = 1; o < 32; o <<= 1) {
            int t = __shfl_up_sync(~0u, inc, o);
            if (lane >= o) inc += t;
        }
        int tot = __shfl_sync(~0u, inc, 31);
        int wb = 0;
        if (lane == 31 && tot > 0) wb = atomicAdd(&g_tot2, tot);
        wb = __shfl_sync(~0u, wb, 31);
        if (in2) g_base2[i] = wb + inc - deg;
    }
}

// ---------------- 5: CSR fill -------------------------------------------------
__global__ void fill_k(const int* __restrict__ ei)
{
    int e = blockIdx.x * blockDim.x + threadIdx.x;
    if (e >= N_EDGES) return;
    int d = ei[N_EDGES + e], s = ei[e];
    if (g_need1[d]) g_csr1[g_base1[d] + atomicAdd(&g_fc1[d], 1)] = s;
    if (g_need2[d]) g_csr2[g_base2[d] + atomicAdd(&g_fc2[d], 1)] = s;
}

// ---------------- 6: layer-1 gather with INLINE scores + cleanup -------------
__global__ __launch_bounds__(256)
void gather1_k(const float* __restrict__ uT, const float* __restrict__ iT)
{
    int i    = (blockIdx.x * blockDim.x + threadIdx.x) >> 5;
    int lane = threadIdx.x & 31;
    if (i >= g_cnt1) return;
    int d = g_list1[i];

    float wsr[4][4], wdr[4][4];
    #pragma unroll
    for (int h = 0; h < 4; h++)
        #pragma unroll
        for (int j = 0; j < 4; j++) {
            wsr[h][j] = g_ws1[h * DIM + lane + 32 * j];
            wdr[h][j] = g_wd1[h * DIM + lane + 32 * j];
        }

    const float* xd = xrow(d, uT, iT);
    float v[4] = {xd[lane], xd[lane + 32], xd[lane + 64], xd[lane + 96]};

    float bd[4], den[4];
    float acc[4][4];
    #pragma unroll
    for (int h = 0; h < 4; h++) {
        float ad = wsum(v[0] * wsr[h][0] + v[1] * wsr[h][1] +
                        v[2] * wsr[h][2] + v[3] * wsr[h][3]);
        bd[h]    = wsum(v[0] * wdr[h][0] + v[1] * wdr[h][1] +
                        v[2] * wdr[h][2] + v[3] * wdr[h][3]);
        float w = expf(lrelu(ad + bd[h]));
        den[h] = w;
        #pragma unroll
        for (int j = 0; j < 4; j++) acc[h][j] = w * v[j];
    }

    int base = g_base1[d], deg = g_deg1[d];
    for (int k = base; k < base + deg; k++) {
        int s = g_csr1[k];
        const float* xs = xrow(s, uT, iT);
        float e0 = xs[lane];      float e1 = xs[lane + 32];
        float e2 = xs[lane + 64]; float e3 = xs[lane + 96];
        #pragma unroll
        for (int h = 0; h < 4; h++) {
            float as = wsum(e0 * wsr[h][0] + e1 * wsr[h][1] +
                            e2 * wsr[h][2] + e3 * wsr[h][3]);
            float q = expf(lrelu(as + bd[h]));
            den[h] += q;
            acc[h][0] += q * e0; acc[h][1] += q * e1;
            acc[h][2] += q * e2; acc[h][3] += q * e3;
        }
    }

    #pragma unroll
    for (int h = 0; h < 4; h++) {
        float inv = 1.f / (den[h] + 1e-16f);
        float* o = g_big + ((size_t)(d * 4 + h)) * DIM;
        o[lane]      = acc[h][0] * inv;  o[lane + 32] = acc[h][1] * inv;
        o[lane + 64] = acc[h][2] * inv;  o[lane + 96] = acc[h][3] * inv;
    }
    if (lane == 0) { g_need1[d] = 0; g_deg1[d] = 0; g_fc1[d] = 0; }   // self-clean
}

// ---------------- 7: GEMM-1 (f32x2): h1 = elu(aggH @ W1blk + bias) -----------
__global__ __launch_bounds__(256)
void gemm1_k(const float* __restrict__ W1, const float* __restrict__ bias1)
{
    __shared__ float As[32][132];
    __shared__ float Bs[32][36];
    __shared__ int   sNode[128];

    const int cnt  = g_cnt1;
    const int row0 = blockIdx.x * 128;
    if (row0 >= cnt) return;
    const int h   = blockIdx.y;
    const int tid = threadIdx.x;
    const int tx  = tid & 7;
    const int ty  = tid >> 3;

    if (tid < 128) {
        int r = row0 + tid;
        sNode[tid] = (r < cnt) ? g_list1[r] : g_list1[0];
    }
    __syncthreads();

    // acc2[p][j] = packed (row 2p, row 2p+1) accumulator for col j
    unsigned long long acc2[2][4];
    #pragma unroll
    for (int p = 0; p < 2; p++)
        #pragma unroll
        for (int j = 0; j < 4; j++) acc2[p][j] = 0ull;

    const int lr = tid & 127;
    const int lq = (tid >> 7) * 16;
    const int bkr = tid >> 3;
    const int bbc = (tid & 7) * 4;

    for (int kk = 0; kk < DIM; kk += 32) {
        const bool valid = (row0 + lr < cnt);
        const float* ap = g_big + ((size_t)(sNode[lr] * 4 + h)) * DIM + kk + lq;
        #pragma unroll
        for (int q = 0; q < 4; q++) {
            float4 vv = valid ? *(const float4*)(ap + q * 4)
                              : make_float4(0.f, 0.f, 0.f, 0.f);
            As[lq + q * 4 + 0][lr] = vv.x;
            As[lq + q * 4 + 1][lr] = vv.y;
            As[lq + q * 4 + 2][lr] = vv.z;
            As[lq + q * 4 + 3][lr] = vv.w;
        }
        *(float4*)&Bs[bkr][bbc] =
            *(const float4*)(W1 + (size_t)(kk + bkr) * DIM + h * 32 + bbc);
        __syncthreads();

        #pragma unroll
        for (int k = 0; k < 32; k++) {
            // 4 consecutive A rows -> 2 packed b64 operands (16B-aligned: 132*4, ty*16)
            ulonglong2 apair = *(const ulonglong2*)&As[k][ty * 4];
            float4 b4 = *(const float4*)&Bs[k][tx * 4];
            unsigned long long bb0 = bcast2(b4.x), bb1 = bcast2(b4.y);
            unsigned long long bb2 = bcast2(b4.z), bb3 = bcast2(b4.w);
            ffma2(acc2[0][0], apair.x, bb0); ffma2(acc2[0][1], apair.x, bb1);
            ffma2(acc2[0][2], apair.x, bb2); ffma2(acc2[0][3], apair.x, bb3);
            ffma2(acc2[1][0], apair.y, bb0); ffma2(acc2[1][1], apair.y, bb1);
            ffma2(acc2[1][2], apair.y, bb2); ffma2(acc2[1][3], apair.y, bb3);
        }
        __syncthreads();
    }

    const int colb = h * 32 + tx * 4;
    float b0 = bias1[colb], b1 = bias1[colb + 1], b2 = bias1[colb + 2], b3 = bias1[colb + 3];
    #pragma unroll
    for (int p = 0; p < 2; p++) {
        #pragma unroll
        for (int half = 0; half < 2; half++) {
            int row = ty * 4 + p * 2 + half;
            if (row0 + row < cnt) {
                float c0 = half ? hi2(acc2[p][0]) : lo2(acc2[p][0]);
                float c1 = half ? hi2(acc2[p][1]) : lo2(acc2[p][1]);
                float c2 = half ? hi2(acc2[p][2]) : lo2(acc2[p][2]);
                float c3 = half ? hi2(acc2[p][3]) : lo2(acc2[p][3]);
                float* o = g_h1 + (size_t)sNode[row] * DIM + colb;
                *(float4*)o = make_float4(eluf(c0 + b0), eluf(c1 + b1),
                                          eluf(c2 + b2), eluf(c3 + b3));
            }
        }
    }
}

// ---------------- 8: layer-2 gather with INLINE scores + cleanup -------------
__global__ __launch_bounds__(256)
void gather2_k()
{
    int i    = (blockIdx.x * blockDim.x + threadIdx.x) >> 5;
    int lane = threadIdx.x & 31;
    if (i >= g_cnt2) return;
    int d = g_list2[i];

    float wr[4], wdr[4];
    #pragma unroll
    for (int j = 0; j < 4; j++) {
        wr[j]  = g_ws2[lane + 32 * j];
        wdr[j] = g_wd2[lane + 32 * j];
    }

    const float* hd = g_h1 + (size_t)d * DIM;
    float v0 = hd[lane];      float v1 = hd[lane + 32];
    float v2 = hd[lane + 64]; float v3 = hd[lane + 96];
    float ad  = wsum(v0 * wr[0] + v1 * wr[1] + v2 * wr[2] + v3 * wr[3]);
    float b2d = wsum(v0 * wdr[0] + v1 * wdr[1] + v2 * wdr[2] + v3 * wdr[3]);
    float w = expf(lrelu(ad + b2d));
    float den = w;
    float a0 = w * v0, a1 = w * v1, a2 = w * v2, a3 = w * v3;

    int base = g_base2[d], deg = g_deg2[d];
    for (int k = base; k < base + deg; k++) {
        int s = g_csr2[k];
        const float* hs = g_h1 + (size_t)s * DIM;
        float e0 = hs[lane];      float e1 = hs[lane + 32];
        float e2 = hs[lane + 64]; float e3 = hs[lane + 96];
        float as = wsum(e0 * wr[0] + e1 * wr[1] + e2 * wr[2] + e3 * wr[3]);
        float q = expf(lrelu(as + b2d));
        den += q;
        a0 += q * e0; a1 += q * e1; a2 += q * e2; a3 += q * e3;
    }
    float inv = 1.f / (den + 1e-16f);
    float* o = g_big + (size_t)d * DIM;
    o[lane]      = a0 * inv;  o[lane + 32] = a1 * inv;
    o[lane + 64] = a2 * inv;  o[lane + 96] = a3 * inv;
    if (lane == 0) { g_need2[d] = 0; g_deg2[d] = 0; g_fc2[d] = 0; }   // self-clean
}

// ---------------- 9: GEMM-2 (f32x2): h2 = elu(agg2 @ W2 + bias2) -------------
__global__ __launch_bounds__(256)
void gemm2_k(const float* __restrict__ W2, const float* __restrict__ bias2)
{
    __shared__ float As[16][132];
    __shared__ float Bs[16][128];
    __shared__ int   sNode[128];

    const int cnt  = g_cnt2;
    const int row0 = blockIdx.x * 128;
    if (row0 >= cnt) return;
    const int tid = threadIdx.x;
    const int tx  = tid & 15;
    const int ty  = tid >> 4;

    if (tid < 128) {
        int r = row0 + tid;
        sNode[tid] = (r < cnt) ? g_list2[r] : g_list2[0];
    }
    __syncthreads();

    // acc2[p][j] = packed (row 2p, row 2p+1) accumulator for col j (8 cols)
    unsigned long long acc2[4][8];
    #pragma unroll
    for (int p = 0; p < 4; p++)
        #pragma unroll
        for (int j = 0; j < 8; j++) acc2[p][j] = 0ull;

    const int lr = tid & 127;
    const int lq = (tid >> 7) * 8;
    const int bkr = tid >> 4;
    const int bbc = (tid & 15) * 8;

    for (int kk = 0; kk < DIM; kk += 16) {
        const bool valid = (row0 + lr < cnt);
        const float* ap = g_big + (size_t)sNode[lr] * DIM + kk + lq;
        #pragma unroll
        for (int q = 0; q < 2; q++) {
            float4 vv = valid ? *(const float4*)(ap + q * 4)
                              : make_float4(0.f, 0.f, 0.f, 0.f);
            As[lq + q * 4 + 0][lr] = vv.x;
            As[lq + q * 4 + 1][lr] = vv.y;
            As[lq + q * 4 + 2][lr] = vv.z;
            As[lq + q * 4 + 3][lr] = vv.w;
        }
        *(float4*)&Bs[bkr][bbc]     = *(const float4*)(W2 + (size_t)(kk + bkr) * DIM + bbc);
        *(float4*)&Bs[bkr][bbc + 4] = *(const float4*)(W2 + (size_t)(kk + bkr) * DIM + bbc + 4);
        __syncthreads();

        #pragma unroll
        for (int k = 0; k < 16; k++) {
            // 8 consecutive A rows -> 4 packed b64 operands
            ulonglong2 ap01 = *(const ulonglong2*)&As[k][ty * 8];
            ulonglong2 ap23 = *(const ulonglong2*)&As[k][ty * 8 + 4];
            float4 b0 = *(const float4*)&Bs[k][tx * 8];
            float4 b1 = *(const float4*)&Bs[k][tx * 8 + 4];
            unsigned long long bb[8] = {
                bcast2(b0.x), bcast2(b0.y), bcast2(b0.z), bcast2(b0.w),
                bcast2(b1.x), bcast2(b1.y), bcast2(b1.z), bcast2(b1.w)};
            #pragma unroll
            for (int j = 0; j < 8; j++) {
                ffma2(acc2[0][j], ap01.x, bb[j]);
                ffma2(acc2[1][j], ap01.y, bb[j]);
                ffma2(acc2[2][j], ap23.x, bb[j]);
                ffma2(acc2[3][j], ap23.y, bb[j]);
            }
        }
        __syncthreads();
    }

    const int colb = tx * 8;
    float bb[8];
    #pragma unroll
    for (int j = 0; j < 8; j++) bb[j] = bias2[colb + j];
    #pragma unroll
    for (int p = 0; p < 4; p++) {
        #pragma unroll
        for (int half = 0; half < 2; half++) {
            int row = ty * 8 + p * 2 + half;
            if (row0 + row < cnt) {
                float c[8];
                #pragma unroll
                for (int j = 0; j < 8; j++)
                    c[j] = half ? hi2(acc2[p][j]) : lo2(acc2[p][j]);
                float* o = g_h1 + (size_t)sNode[row] * DIM + colb;   // h2 aliases h1
                *(float4*)(o) = make_float4(
                    eluf(c[0] + bb[0]), eluf(c[1] + bb[1]),
                    eluf(c[2] + bb[2]), eluf(c[3] + bb[3]));
                *(float4*)(o + 4) = make_float4(
                    eluf(c[4] + bb[4]), eluf(c[5] + bb[5]),
                    eluf(c[6] + bb[6]), eluf(c[7] + bb[7]));
            }
        }
    }
}

// ---------------- 10: final dot + sigmoid ------------------------------------
__global__ __launch_bounds__(256)
void final_k(const int* __restrict__ uidx, const int* __restrict__ iidx,
             float* __restrict__ res)
{
    int b    = (blockIdx.x * blockDim.x + threadIdx.x) >> 5;
    int lane = threadIdx.x & 31;
    if (b >= BATCH) return;
    const float* ru = g_h1 + (size_t)uidx[b] * DIM;
    const float* rv = g_h1 + (size_t)(iidx[b] + NUM_USERS) * DIM;
    float dot = ru[lane]      * rv[lane]
              + ru[lane + 32] * rv[lane + 32]
              + ru[lane + 64] * rv[lane + 64]
              + ru[lane + 96] * rv[lane + 96];
    dot = wsum(dot);
    if (lane == 0) res[b] = 1.f / (1.f + expf(-dot));
}

// ---------------- launch -----------------------------------------------------
extern "C" void kernel_launch(void* const* d_in, const int* in_sizes, int n_in,
                              void* d_out, int out_size)
{
    const int*   uidx  = (const int*)  d_in[0];
    const int*   iidx  = (const int*)  d_in[1];
    const int*   ei    = (const int*)  d_in[2];
    const float* userT = (const float*)d_in[3];
    const float* itemT = (const float*)d_in[4];
    const float* W1    = (const float*)d_in[5];
    const float* attS1 = (const float*)d_in[6];
    const float* attD1 = (const float*)d_in[7];
    const float* bias1 = (const float*)d_in[8];
    const float* W2    = (const float*)d_in[9];
    const float* attS2 = (const float*)d_in[10];
    const float* attD2 = (const float*)d_in[11];
    const float* bias2 = (const float*)d_in[12];
    float* res = (float*)d_out;

    const int nodeB = (N_NODES + 255) / 256;
    const int edgeB = (N_EDGES + 255) / 256;

    prep_k       <<<1 + (BATCH + 255) / 256, 256>>>(W1, attS1, attD1,
                                                    W2, attS2, attD2, uidx, iidx);
    mark1_k      <<<edgeB, 256>>>(ei);
    markC_k      <<<edgeB, 256>>>(ei);
    compactalloc_k<<<nodeB, 256>>>();
    fill_k       <<<edgeB, 256>>>(ei);

    gather1_k    <<<(MAXL1 + 7) / 8, 256>>>(userT, itemT);
    gemm1_k      <<<dim3((MAXL1 + 127) / 128, 4), 256>>>(W1, bias1);

    gather2_k    <<<(MAXL2 + 7) / 8, 256>>>();
    gemm2_k      <<<(MAXL2 + 127) / 128, 256>>>(W2, bias2);

    final_k      <<<(BATCH + 7) / 8, 256>>>(uidx, iidx, res);
}

// round 11
// speedup vs baseline: 1.0844x; 1.0844x over previous
#include <cuda_runtime.h>
#include <math.h>
#include <stdint.h>

#define NUM_USERS 162541
#define NUM_ITEMS 59047
#define N_NODES   221588
#define DIM       128
#define N_EDGES   100000
#define BATCH     16384
#define MAXL1     132768
#define MAXL2     32768
#define NBLK      296        // persistent grid: 2 blocks/SM on 148 SMs -> all resident

// ---------------- scratch (device globals; device-code use ONLY) ------------
// Invariant: masks/degrees/counters are ZERO on entry (zero-init at load;
// every call cleans exactly what it dirtied).
__device__ float g_h1 [(size_t)N_NODES * DIM];   // h1; later h2
__device__ unsigned char g_need1[N_NODES], g_need2[N_NODES];
__device__ int g_list1[MAXL1], g_list2[MAXL2];
__device__ int g_cnt1, g_cnt2, g_tot1, g_tot2;
__device__ int g_deg1[N_NODES], g_deg2[N_NODES];
__device__ int g_base1[N_NODES], g_base2[N_NODES];
__device__ int g_fc1[N_NODES], g_fc2[N_NODES];
__device__ int g_csr1[N_EDGES], g_csr2[N_EDGES];
__device__ float g_ws1[4 * DIM], g_wd1[4 * DIM];
__device__ float g_ws2[DIM],     g_wd2[DIM];
// software grid barrier state (g_gen monotonic across replays; g_cnt self-resets)
__device__ unsigned g_gen, g_cntb;

// ---------------- helpers ---------------------------------------------------
__device__ __forceinline__ float eluf(float x)  { return x > 0.f ? x : expm1f(x); }
__device__ __forceinline__ float lrelu(float x) { return x > 0.f ? x : 0.2f * x; }
__device__ __forceinline__ float wsum(float v) {
    #pragma unroll
    for (int o = 16; o; o >>= 1) v += __shfl_xor_sync(0xffffffffu, v, o);
    return v;
}
__device__ __forceinline__ const float* xrow(int n, const float* uT, const float* iT) {
    return (n < NUM_USERS) ? uT + (size_t)n * DIM
                           : iT + (size_t)(n - NUM_USERS) * DIM;
}
__device__ __forceinline__ void gridbar() {
    __syncthreads();
    if (threadIdx.x == 0) {
        __threadfence();
        unsigned gen = *((volatile unsigned*)&g_gen);
        if (atomicAdd(&g_cntb, 1) == NBLK - 1) {
            g_cntb = 0;
            __threadfence();
            atomicAdd(&g_gen, 1);            // release
        } else {
            while (*((volatile unsigned*)&g_gen) == gen) { }
        }
        __threadfence();
    }
    __syncthreads();
}

// ---------------- 1: persistent graph-prep (5 phases, 1 launch) --------------
__global__ __launch_bounds__(256)
void megaprep_k(const float* __restrict__ W1, const float* __restrict__ aS1,
                const float* __restrict__ aD1, const float* __restrict__ W2,
                const float* __restrict__ aS2, const float* __restrict__ aD2,
                const int* __restrict__ uidx, const int* __restrict__ iidx,
                const int* __restrict__ ei)
{
    __shared__ int w1[8], w2[8];
    __shared__ int base1, base2;
    const int tid = threadIdx.x;
    const int gstride = NBLK * 256;

    // ---- P0: weight fold + counter reset + batch marks ----
    if (blockIdx.x == 0) {
        if (tid == 128) { g_cnt1 = 0; g_cnt2 = 0; g_tot1 = 0; g_tot2 = 0; }
        if (tid < 128) {
            int k = tid;
            #pragma unroll
            for (int h = 0; h < 4; h++) {
                float s = 0.f, d = 0.f;
                #pragma unroll
                for (int c = 0; c < 32; c++) {
                    float w = W1[k * DIM + h * 32 + c];
                    s = fmaf(w, aS1[h * 32 + c], s);
                    d = fmaf(w, aD1[h * 32 + c], d);
                }
                g_ws1[h * DIM + k] = s;
                g_wd1[h * DIM + k] = d;
            }
            float s2 = 0.f, d2 = 0.f;
            for (int j = 0; j < DIM; j++) {
                float w = W2[k * DIM + j];
                s2 = fmaf(w, aS2[j], s2);
                d2 = fmaf(w, aD2[j], d2);
            }
            g_ws2[k] = s2;
            g_wd2[k] = d2;
        }
    }
    for (int i = blockIdx.x * 256 + tid; i < BATCH; i += gstride) {
        int u = uidx[i], v = iidx[i] + NUM_USERS;
        g_need2[u] = 1; g_need1[u] = 1;
        g_need2[v] = 1; g_need1[v] = 1;
    }
    gridbar();

    // ---- P1: need1 |= srcs of edges into need2 ----
    for (int e = blockIdx.x * 256 + tid; e < N_EDGES; e += gstride)
        if (g_need2[ei[N_EDGES + e]]) g_need1[ei[e]] = 1;
    gridbar();

    // ---- P2: degree histograms ----
    for (int e = blockIdx.x * 256 + tid; e < N_EDGES; e += gstride) {
        int d = ei[N_EDGES + e];
        if (g_need1[d]) atomicAdd(&g_deg1[d], 1);
        if (g_need2[d]) atomicAdd(&g_deg2[d], 1);
    }
    gridbar();

    // ---- P3: list compaction + CSR base allocation ----
    for (int cb = blockIdx.x; cb * 256 < N_NODES; cb += NBLK) {
        int i = cb * 256 + tid;
        int w = tid >> 5, lane = tid & 31;
        bool in1 = (i < N_NODES) && g_need1[i];
        bool in2 = (i < N_NODES) && g_need2[i];
        unsigned m1 = __ballot_sync(~0u, in1);
        unsigned m2 = __ballot_sync(~0u, in2);
        if (lane == 0) { w1[w] = __popc(m1); w2[w] = __popc(m2); }
        __syncthreads();
        if (tid == 0) {
            int t1 = 0, t2 = 0;
            #pragma unroll
            for (int k = 0; k < 8; k++) {
                int v1 = w1[k]; w1[k] = t1; t1 += v1;
                int v2 = w2[k]; w2[k] = t2; t2 += v2;
            }
            base1 = (t1 > 0) ? atomicAdd(&g_cnt1, t1) : 0;
            base2 = (t2 > 0) ? atomicAdd(&g_cnt2, t2) : 0;
        }
        __syncthreads();
        unsigned lm = (1u << lane) - 1u;
        if (in1) g_list1[base1 + w1[w] + __popc(m1 & lm)] = i;
        if (in2) g_list2[base2 + w2[w] + __popc(m2 & lm)] = i;
        {
            int deg = in1 ? g_deg1[i] : 0;
            int inc = deg;
            #pragma unroll
            for (int o = 1; o < 32; o <<= 1) {
                int t = __shfl_up_sync(~0u, inc, o);
                if (lane >= o) inc += t;
            }
            int tot = __shfl_sync(~0u, inc, 31);
            int wb = 0;
            if (lane == 31 && tot > 0) wb = atomicAdd(&g_tot1, tot);
            wb = __shfl_sync(~0u, wb, 31);
            if (in1) g_base1[i] = wb + inc - deg;
        }
        {
            int deg = in2 ? g_deg2[i] : 0;
            int inc = deg;
            #pragma unroll
            for (int o = 1; o < 32; o <<= 1) {
                int t = __shfl_up_sync(~0u, inc, o);
                if (lane >= o) inc += t;
            }
            int tot = __shfl_sync(~0u, inc, 31);
            int wb = 0;
            if (lane == 31 && tot > 0) wb = atomicAdd(&g_tot2, tot);
            wb = __shfl_sync(~0u, wb, 31);
            if (in2) g_base2[i] = wb + inc - deg;
        }
        __syncthreads();      // shared reuse next iteration
    }
    gridbar();

    // ---- P4: CSR fill ----
    for (int e = blockIdx.x * 256 + tid; e < N_EDGES; e += gstride) {
        int d = ei[N_EDGES + e], s = ei[e];
        if (g_need1[d]) g_csr1[g_base1[d] + atomicAdd(&g_fc1[d], 1)] = s;
        if (g_need2[d]) g_csr2[g_base2[d] + atomicAdd(&g_fc2[d], 1)] = s;
    }
}

// ---------------- 2: fused layer-1 gather + GEMM (agg stays in shared) -------
// block = 32 need1 nodes. smem: sA[32*4][129] agg rows, sB[16][128] W1 chunk.
#define SM1_SA   (32 * 4 * 129)
#define SM1_SB   (16 * 128)
#define SMEM1    ((SM1_SA + SM1_SB) * 4 + 32 * 4)
__global__ __launch_bounds__(256)
void fused1_k(const float* __restrict__ uT, const float* __restrict__ iT,
              const float* __restrict__ W1, const float* __restrict__ bias1)
{
    extern __shared__ float smem[];
    float* sA = smem;                    // row r = slot*4+h, stride 129
    float* sB = smem + SM1_SA;
    int*   sNode = (int*)(smem + SM1_SA + SM1_SB);

    const int cnt  = g_cnt1;
    const int row0 = blockIdx.x * 32;
    if (row0 >= cnt) return;
    const int tid  = threadIdx.x;
    const int w    = tid >> 5, lane = tid & 31;

    if (tid < 32) sNode[tid] = (row0 + tid < cnt) ? g_list1[row0 + tid] : -1;
    __syncthreads();

    // ---- gather phase: warp w -> nodes w*4 .. w*4+3 ----
    {
        float wsr[4][4], wdr[4][4];
        #pragma unroll
        for (int h = 0; h < 4; h++)
            #pragma unroll
            for (int j = 0; j < 4; j++) {
                wsr[h][j] = g_ws1[h * DIM + lane + 32 * j];
                wdr[h][j] = g_wd1[h * DIM + lane + 32 * j];
            }
        for (int j4 = 0; j4 < 4; j4++) {
            int slot = w * 4 + j4;
            int d = sNode[slot];
            if (d < 0) continue;                     // warp-uniform
            const float* xd = xrow(d, uT, iT);
            float v[4] = {xd[lane], xd[lane + 32], xd[lane + 64], xd[lane + 96]};
            float bd[4], den[4], acc[4][4];
            #pragma unroll
            for (int h = 0; h < 4; h++) {
                float ad = wsum(v[0] * wsr[h][0] + v[1] * wsr[h][1] +
                                v[2] * wsr[h][2] + v[3] * wsr[h][3]);
                bd[h]    = wsum(v[0] * wdr[h][0] + v[1] * wdr[h][1] +
                                v[2] * wdr[h][2] + v[3] * wdr[h][3]);
                float ww = expf(lrelu(ad + bd[h]));
                den[h] = ww;
                #pragma unroll
                for (int j = 0; j < 4; j++) acc[h][j] = ww * v[j];
            }
            int base = g_base1[d], deg = g_deg1[d];
            for (int k = base; k < base + deg; k++) {
                int s = g_csr1[k];
                const float* xs = xrow(s, uT, iT);
                float e0 = xs[lane];      float e1 = xs[lane + 32];
                float e2 = xs[lane + 64]; float e3 = xs[lane + 96];
                #pragma unroll
                for (int h = 0; h < 4; h++) {
                    float as = wsum(e0 * wsr[h][0] + e1 * wsr[h][1] +
                                    e2 * wsr[h][2] + e3 * wsr[h][3]);
                    float q = expf(lrelu(as + bd[h]));
                    den[h] += q;
                    acc[h][0] += q * e0; acc[h][1] += q * e1;
                    acc[h][2] += q * e2; acc[h][3] += q * e3;
                }
            }
            #pragma unroll
            for (int h = 0; h < 4; h++) {
                float inv = 1.f / (den[h] + 1e-16f);
                float* o = sA + (size_t)(slot * 4 + h) * 129;
                o[lane]      = acc[h][0] * inv;  o[lane + 32] = acc[h][1] * inv;
                o[lane + 64] = acc[h][2] * inv;  o[lane + 96] = acc[h][3] * inv;
            }
            if (lane == 0) { g_need1[d] = 0; g_deg1[d] = 0; g_fc1[d] = 0; }
        }
    }
    __syncthreads();

    // ---- GEMM phase: h = tid>>6; thread covers nodes ng+8i, cols cg*4.. ----
    const int h  = tid >> 6;
    const int t  = tid & 63;
    const int ng = t >> 3;
    const int cg = t & 7;
    float acc[4][4];
    #pragma unroll
    for (int i = 0; i < 4; i++)
        #pragma unroll
        for (int j = 0; j < 4; j++) acc[i][j] = 0.f;

    const int brow = tid >> 4;
    const int bcol = (tid & 15) * 8;
    for (int kk = 0; kk < DIM; kk += 16) {
        *(float4*)&sB[brow * 128 + bcol]     = *(const float4*)(W1 + (size_t)(kk + brow) * DIM + bcol);
        *(float4*)&sB[brow * 128 + bcol + 4] = *(const float4*)(W1 + (size_t)(kk + brow) * DIM + bcol + 4);
        __syncthreads();
        #pragma unroll
        for (int k = 0; k < 16; k++) {
            float4 b4 = *(const float4*)&sB[k * 128 + h * 32 + cg * 4];
            #pragma unroll
            for (int i = 0; i < 4; i++) {
                float a = sA[(size_t)((ng + 8 * i) * 4 + h) * 129 + kk + k];
                acc[i][0] = fmaf(a, b4.x, acc[i][0]);
                acc[i][1] = fmaf(a, b4.y, acc[i][1]);
                acc[i][2] = fmaf(a, b4.z, acc[i][2]);
                acc[i][3] = fmaf(a, b4.w, acc[i][3]);
            }
        }
        __syncthreads();
    }

    const int colb = h * 32 + cg * 4;
    float b0 = bias1[colb], b1 = bias1[colb + 1], b2 = bias1[colb + 2], b3 = bias1[colb + 3];
    #pragma unroll
    for (int i = 0; i < 4; i++) {
        int slot = ng + 8 * i;
        if (row0 + slot < cnt) {
            float* o = g_h1 + (size_t)sNode[slot] * DIM + colb;
            *(float4*)o = make_float4(eluf(acc[i][0] + b0), eluf(acc[i][1] + b1),
                                      eluf(acc[i][2] + b2), eluf(acc[i][3] + b3));
        }
    }
}

// ---------------- 3: fused layer-2 gather + GEMM -----------------------------
// block = 128 need2 nodes. smem: sA[128][129], sB[16][128].
#define SM2_SA   (128 * 129)
#define SM2_SB   (16 * 128)
#define SMEM2    ((SM2_SA + SM2_SB) * 4 + 128 * 4)
__global__ __launch_bounds__(256)
void fused2_k(const float* __restrict__ W2, const float* __restrict__ bias2)
{
    extern __shared__ float smem[];
    float* sA = smem;
    float* sB = smem + SM2_SA;
    int*   sNode = (int*)(smem + SM2_SA + SM2_SB);

    const int cnt  = g_cnt2;
    const int row0 = blockIdx.x * 128;
    if (row0 >= cnt) return;
    const int tid  = threadIdx.x;
    const int w    = tid >> 5, lane = tid & 31;

    if (tid < 128) sNode[tid] = (row0 + tid < cnt) ? g_list2[row0 + tid] : -1;
    __syncthreads();

    // ---- gather phase: warp w -> nodes w*16 .. w*16+15 ----
    {
        float wr[4], wdr[4];
        #pragma unroll
        for (int j = 0; j < 4; j++) {
            wr[j]  = g_ws2[lane + 32 * j];
            wdr[j] = g_wd2[lane + 32 * j];
        }
        for (int j16 = 0; j16 < 16; j16++) {
            int slot = w * 16 + j16;
            int d = sNode[slot];
            if (d < 0) continue;                     // warp-uniform
            const float* hd = g_h1 + (size_t)d * DIM;
            float v0 = hd[lane];      float v1 = hd[lane + 32];
            float v2 = hd[lane + 64]; float v3 = hd[lane + 96];
            float ad  = wsum(v0 * wr[0] + v1 * wr[1] + v2 * wr[2] + v3 * wr[3]);
            float b2d = wsum(v0 * wdr[0] + v1 * wdr[1] + v2 * wdr[2] + v3 * wdr[3]);
            float ww = expf(lrelu(ad + b2d));
            float den = ww;
            float a0 = ww * v0, a1 = ww * v1, a2 = ww * v2, a3 = ww * v3;
            int base = g_base2[d], deg = g_deg2[d];
            for (int k = base; k < base + deg; k++) {
                int s = g_csr2[k];
                const float* hs = g_h1 + (size_t)s * DIM;
                float e0 = hs[lane];      float e1 = hs[lane + 32];
                float e2 = hs[lane + 64]; float e3 = hs[lane + 96];
                float as = wsum(e0 * wr[0] + e1 * wr[1] + e2 * wr[2] + e3 * wr[3]);
                float q = expf(lrelu(as + b2d));
                den += q;
                a0 += q * e0; a1 += q * e1; a2 += q * e2; a3 += q * e3;
            }
            float inv = 1.f / (den + 1e-16f);
            float* o = sA + (size_t)slot * 129;
            o[lane]      = a0 * inv;  o[lane + 32] = a1 * inv;
            o[lane + 64] = a2 * inv;  o[lane + 96] = a3 * inv;
            if (lane == 0) { g_need2[d] = 0; g_deg2[d] = 0; g_fc2[d] = 0; }
        }
    }
    __syncthreads();

    // ---- GEMM phase: 8x8 micro-tile ----
    const int tx = tid & 15;
    const int ty = tid >> 4;
    float acc[8][8];
    #pragma unroll
    for (int i = 0; i < 8; i++)
        #pragma unroll
        for (int j = 0; j < 8; j++) acc[i][j] = 0.f;

    const int brow = tid >> 4;
    const int bcol = (tid & 15) * 8;
    for (int kk = 0; kk < DIM; kk += 16) {
        *(float4*)&sB[brow * 128 + bcol]     = *(const float4*)(W2 + (size_t)(kk + brow) * DIM + bcol);
        *(float4*)&sB[brow * 128 + bcol + 4] = *(const float4*)(W2 + (size_t)(kk + brow) * DIM + bcol + 4);
        __syncthreads();
        #pragma unroll
        for (int k = 0; k < 16; k++) {
            float4 bl = *(const float4*)&sB[k * 128 + tx * 8];
            float4 bh = *(const float4*)&sB[k * 128 + tx * 8 + 4];
            float b[8] = {bl.x, bl.y, bl.z, bl.w, bh.x, bh.y, bh.z, bh.w};
            #pragma unroll
            for (int i = 0; i < 8; i++) {
                float a = sA[(size_t)(ty * 8 + i) * 129 + kk + k];
                #pragma unroll
                for (int j = 0; j < 8; j++)
                    acc[i][j] = fmaf(a, b[j], acc[i][j]);
            }
        }
        __syncthreads();
    }

    const int colb = tx * 8;
    float bb[8];
    #pragma unroll
    for (int j = 0; j < 8; j++) bb[j] = bias2[colb + j];
    #pragma unroll
    for (int i = 0; i < 8; i++) {
        int row = ty * 8 + i;
        if (row0 + row < cnt) {
            float* o = g_h1 + (size_t)sNode[row] * DIM + colb;   // h2 aliases h1
            *(float4*)(o) = make_float4(
                eluf(acc[i][0] + bb[0]), eluf(acc[i][1] + bb[1]),
                eluf(acc[i][2] + bb[2]), eluf(acc[i][3] + bb[3]));
            *(float4*)(o + 4) = make_float4(
                eluf(acc[i][4] + bb[4]), eluf(acc[i][5] + bb[5]),
                eluf(acc[i][6] + bb[6]), eluf(acc[i][7] + bb[7]));
        }
    }
}

// ---------------- 4: final dot + sigmoid -------------------------------------
__global__ __launch_bounds__(256)
void final_k(const int* __restrict__ uidx, const int* __restrict__ iidx,
             float* __restrict__ res)
{
    int b    = (blockIdx.x * blockDim.x + threadIdx.x) >> 5;
    int lane = threadIdx.x & 31;
    if (b >= BATCH) return;
    const float* ru = g_h1 + (size_t)uidx[b] * DIM;
    const float* rv = g_h1 + (size_t)(iidx[b] + NUM_USERS) * DIM;
    float dot = ru[lane]      * rv[lane]
              + ru[lane + 32] * rv[lane + 32]
              + ru[lane + 64] * rv[lane + 64]
              + ru[lane + 96] * rv[lane + 96];
    dot = wsum(dot);
    if (lane == 0) res[b] = 1.f / (1.f + expf(-dot));
}

// ---------------- launch -----------------------------------------------------
extern "C" void kernel_launch(void* const* d_in, const int* in_sizes, int n_in,
                              void* d_out, int out_size)
{
    const int*   uidx  = (const int*)  d_in[0];
    const int*   iidx  = (const int*)  d_in[1];
    const int*   ei    = (const int*)  d_in[2];
    const float* userT = (const float*)d_in[3];
    const float* itemT = (const float*)d_in[4];
    const float* W1    = (const float*)d_in[5];
    const float* attS1 = (const float*)d_in[6];
    const float* attD1 = (const float*)d_in[7];
    const float* bias1 = (const float*)d_in[8];
    const float* W2    = (const float*)d_in[9];
    const float* attS2 = (const float*)d_in[10];
    const float* attD2 = (const float*)d_in[11];
    const float* bias2 = (const float*)d_in[12];
    float* res = (float*)d_out;

    cudaFuncSetAttribute(fused1_k, cudaFuncAttributeMaxDynamicSharedMemorySize, SMEM1);
    cudaFuncSetAttribute(fused2_k, cudaFuncAttributeMaxDynamicSharedMemorySize, SMEM2);

    megaprep_k<<<NBLK, 256>>>(W1, attS1, attD1, W2, attS2, attD2, uidx, iidx, ei);
    fused1_k  <<<(MAXL1 + 31) / 32,   256, SMEM1>>>(userT, itemT, W1, bias1);
    fused2_k  <<<(MAXL2 + 127) / 128, 256, SMEM2>>>(W2, bias2);
    final_k   <<<(BATCH + 7) / 8, 256>>>(uidx, iidx, res);
}

// round 12
// speedup vs baseline: 1.3389x; 1.2347x over previous
#include <cuda_runtime.h>
#include <math.h>
#include <stdint.h>

#define NUM_USERS 162541
#define NUM_ITEMS 59047
#define N_NODES   221588
#define DIM       128
#define N_EDGES   100000
#define BATCH     16384
#define MAXL1     132768
#define MAXL2     32768
#define NBLK      296        // persistent grid: 2 blocks/SM on 148 SMs
#define SA_STR    132        // sA stride (bank = 4*row + k, conflict-free frags)
#define SB_STR    136        // sB stride (bank = 8*k + n, conflict-free frags)

// ---------------- scratch (device globals; device-code use ONLY) ------------
__device__ float g_h1 [(size_t)N_NODES * DIM];   // h1; later h2
__device__ unsigned char g_need1[N_NODES], g_need2[N_NODES];
__device__ int g_list1[MAXL1], g_list2[MAXL2];
__device__ int g_cnt1, g_cnt2, g_tot1, g_tot2;
__device__ int g_deg1[N_NODES], g_deg2[N_NODES];
__device__ int g_base1[N_NODES], g_base2[N_NODES];
__device__ int g_fc1[N_NODES], g_fc2[N_NODES];
__device__ int g_csr1[N_EDGES], g_csr2[N_EDGES];
__device__ float g_ws1[4 * DIM], g_wd1[4 * DIM];
__device__ float g_ws2[DIM],     g_wd2[DIM];
__device__ unsigned g_gen, g_cntb;

// ---------------- helpers ---------------------------------------------------
__device__ __forceinline__ float eluf(float x)  { return x > 0.f ? x : expm1f(x); }
__device__ __forceinline__ float lrelu(float x) { return x > 0.f ? x : 0.2f * x; }
__device__ __forceinline__ float wsum(float v) {
    #pragma unroll
    for (int o = 16; o; o >>= 1) v += __shfl_xor_sync(0xffffffffu, v, o);
    return v;
}
__device__ __forceinline__ const float* xrow(int n, const float* uT, const float* iT) {
    return (n < NUM_USERS) ? uT + (size_t)n * DIM
                           : iT + (size_t)(n - NUM_USERS) * DIM;
}
__device__ __forceinline__ void mma8(float& c0, float& c1, float& c2, float& c3,
    uint32_t a0, uint32_t a1, uint32_t a2, uint32_t a3, uint32_t b0, uint32_t b1) {
    asm volatile("mma.sync.aligned.m16n8k8.row.col.f32.tf32.tf32.f32 "
        "{%0,%1,%2,%3}, {%4,%5,%6,%7}, {%8,%9}, {%0,%1,%2,%3};\n"
        : "+f"(c0), "+f"(c1), "+f"(c2), "+f"(c3)
        : "r"(a0), "r"(a1), "r"(a2), "r"(a3), "r"(b0), "r"(b1));
}
__device__ __forceinline__ void gridbar() {
    __syncthreads();
    if (threadIdx.x == 0) {
        __threadfence();
        unsigned gen = *((volatile unsigned*)&g_gen);
        if (atomicAdd(&g_cntb, 1) == NBLK - 1) {
            g_cntb = 0;
            __threadfence();
            atomicAdd(&g_gen, 1);
        } else {
            while (*((volatile unsigned*)&g_gen) == gen) { }
        }
        __threadfence();
    }
    __syncthreads();
}

// ---------------- 1: persistent graph-prep (5 phases, 1 launch) --------------
__global__ __launch_bounds__(256)
void megaprep_k(const float* __restrict__ W1, const float* __restrict__ aS1,
                const float* __restrict__ aD1, const float* __restrict__ W2,
                const float* __restrict__ aS2, const float* __restrict__ aD2,
                const int* __restrict__ uidx, const int* __restrict__ iidx,
                const int* __restrict__ ei)
{
    __shared__ int w1[8], w2[8];
    __shared__ int base1, base2;
    const int tid = threadIdx.x;
    const int gstride = NBLK * 256;

    if (blockIdx.x == 0) {
        if (tid == 128) { g_cnt1 = 0; g_cnt2 = 0; g_tot1 = 0; g_tot2 = 0; }
        if (tid < 128) {
            int k = tid;
            #pragma unroll
            for (int h = 0; h < 4; h++) {
                float s = 0.f, d = 0.f;
                #pragma unroll
                for (int c = 0; c < 32; c++) {
                    float w = W1[k * DIM + h * 32 + c];
                    s = fmaf(w, aS1[h * 32 + c], s);
                    d = fmaf(w, aD1[h * 32 + c], d);
                }
                g_ws1[h * DIM + k] = s;
                g_wd1[h * DIM + k] = d;
            }
            float s2 = 0.f, d2 = 0.f;
            for (int j = 0; j < DIM; j++) {
                float w = W2[k * DIM + j];
                s2 = fmaf(w, aS2[j], s2);
                d2 = fmaf(w, aD2[j], d2);
            }
            g_ws2[k] = s2;
            g_wd2[k] = d2;
        }
    }
    for (int i = blockIdx.x * 256 + tid; i < BATCH; i += gstride) {
        int u = uidx[i], v = iidx[i] + NUM_USERS;
        g_need2[u] = 1; g_need1[u] = 1;
        g_need2[v] = 1; g_need1[v] = 1;
    }
    gridbar();

    for (int e = blockIdx.x * 256 + tid; e < N_EDGES; e += gstride)
        if (g_need2[ei[N_EDGES + e]]) g_need1[ei[e]] = 1;
    gridbar();

    for (int e = blockIdx.x * 256 + tid; e < N_EDGES; e += gstride) {
        int d = ei[N_EDGES + e];
        if (g_need1[d]) atomicAdd(&g_deg1[d], 1);
        if (g_need2[d]) atomicAdd(&g_deg2[d], 1);
    }
    gridbar();

    for (int cb = blockIdx.x; cb * 256 < N_NODES; cb += NBLK) {
        int i = cb * 256 + tid;
        int w = tid >> 5, lane = tid & 31;
        bool in1 = (i < N_NODES) && g_need1[i];
        bool in2 = (i < N_NODES) && g_need2[i];
        unsigned m1 = __ballot_sync(~0u, in1);
        unsigned m2 = __ballot_sync(~0u, in2);
        if (lane == 0) { w1[w] = __popc(m1); w2[w] = __popc(m2); }
        __syncthreads();
        if (tid == 0) {
            int t1 = 0, t2 = 0;
            #pragma unroll
            for (int k = 0; k < 8; k++) {
                int v1 = w1[k]; w1[k] = t1; t1 += v1;
                int v2 = w2[k]; w2[k] = t2; t2 += v2;
            }
            base1 = (t1 > 0) ? atomicAdd(&g_cnt1, t1) : 0;
            base2 = (t2 > 0) ? atomicAdd(&g_cnt2, t2) : 0;
        }
        __syncthreads();
        unsigned lm = (1u << lane) - 1u;
        if (in1) g_list1[base1 + w1[w] + __popc(m1 & lm)] = i;
        if (in2) g_list2[base2 + w2[w] + __popc(m2 & lm)] = i;
        {
            int deg = in1 ? g_deg1[i] : 0;
            int inc = deg;
            #pragma unroll
            for (int o = 1; o < 32; o <<= 1) {
                int t = __shfl_up_sync(~0u, inc, o);
                if (lane >= o) inc += t;
            }
            int tot = __shfl_sync(~0u, inc, 31);
            int wb = 0;
            if (lane == 31 && tot > 0) wb = atomicAdd(&g_tot1, tot);
            wb = __shfl_sync(~0u, wb, 31);
            if (in1) g_base1[i] = wb + inc - deg;
        }
        {
            int deg = in2 ? g_deg2[i] : 0;
            int inc = deg;
            #pragma unroll
            for (int o = 1; o < 32; o <<= 1) {
                int t = __shfl_up_sync(~0u, inc, o);
                if (lane >= o) inc += t;
            }
            int tot = __shfl_sync(~0u, inc, 31);
            int wb = 0;
            if (lane == 31 && tot > 0) wb = atomicAdd(&g_tot2, tot);
            wb = __shfl_sync(~0u, wb, 31);
            if (in2) g_base2[i] = wb + inc - deg;
        }
        __syncthreads();
    }
    gridbar();

    for (int e = blockIdx.x * 256 + tid; e < N_EDGES; e += gstride) {
        int d = ei[N_EDGES + e], s = ei[e];
        if (g_need1[d]) g_csr1[g_base1[d] + atomicAdd(&g_fc1[d], 1)] = s;
        if (g_need2[d]) g_csr2[g_base2[d] + atomicAdd(&g_fc2[d], 1)] = s;
    }
}

// ---------------- 2: fused layer-1 gather + TF32-mma GEMM --------------------
// block = 32 need1 nodes. sA layout: [h][slot][k], slot-stride SA_STR.
#define SM1_SA   (4 * 32 * SA_STR)
#define SM1_SB   (16 * SB_STR)
#define SMEM1    ((SM1_SA + SM1_SB) * 4 + 32 * 4)
__global__ __launch_bounds__(256)
void fused1_k(const float* __restrict__ uT, const float* __restrict__ iT,
              const float* __restrict__ W1, const float* __restrict__ bias1)
{
    extern __shared__ float smem[];
    float* sA = smem;
    float* sB = smem + SM1_SA;
    int*   sNode = (int*)(smem + SM1_SA + SM1_SB);

    const int cnt  = g_cnt1;
    const int row0 = blockIdx.x * 32;
    if (row0 >= cnt) return;
    const int tid  = threadIdx.x;
    const int w    = tid >> 5, lane = tid & 31;

    if (tid < 32) sNode[tid] = (row0 + tid < cnt) ? g_list1[row0 + tid] : -1;
    __syncthreads();

    // ---- gather phase: warp w -> nodes w*4 .. w*4+3 ----
    {
        float wsr[4][4], wdr[4][4];
        #pragma unroll
        for (int h = 0; h < 4; h++)
            #pragma unroll
            for (int j = 0; j < 4; j++) {
                wsr[h][j] = g_ws1[h * DIM + lane + 32 * j];
                wdr[h][j] = g_wd1[h * DIM + lane + 32 * j];
            }
        for (int j4 = 0; j4 < 4; j4++) {
            int slot = w * 4 + j4;
            int d = sNode[slot];
            if (d < 0) {   // zero-fill so GEMM sees no garbage
                #pragma unroll
                for (int h = 0; h < 4; h++) {
                    float* o = sA + (size_t)(h * 32 + slot) * SA_STR;
                    o[lane] = 0.f; o[lane + 32] = 0.f;
                    o[lane + 64] = 0.f; o[lane + 96] = 0.f;
                }
                continue;
            }
            const float* xd = xrow(d, uT, iT);
            float v[4] = {xd[lane], xd[lane + 32], xd[lane + 64], xd[lane + 96]};
            float bd[4], den[4], acc[4][4];
            #pragma unroll
            for (int h = 0; h < 4; h++) {
                float ad = wsum(v[0] * wsr[h][0] + v[1] * wsr[h][1] +
                                v[2] * wsr[h][2] + v[3] * wsr[h][3]);
                bd[h]    = wsum(v[0] * wdr[h][0] + v[1] * wdr[h][1] +
                                v[2] * wdr[h][2] + v[3] * wdr[h][3]);
                float ww = expf(lrelu(ad + bd[h]));
                den[h] = ww;
                #pragma unroll
                for (int j = 0; j < 4; j++) acc[h][j] = ww * v[j];
            }
            int base = g_base1[d], deg = g_deg1[d];
            for (int k = base; k < base + deg; k++) {
                int s = g_csr1[k];
                const float* xs = xrow(s, uT, iT);
                float e0 = xs[lane];      float e1 = xs[lane + 32];
                float e2 = xs[lane + 64]; float e3 = xs[lane + 96];
                #pragma unroll
                for (int h = 0; h < 4; h++) {
                    float as = wsum(e0 * wsr[h][0] + e1 * wsr[h][1] +
                                    e2 * wsr[h][2] + e3 * wsr[h][3]);
                    float q = expf(lrelu(as + bd[h]));
                    den[h] += q;
                    acc[h][0] += q * e0; acc[h][1] += q * e1;
                    acc[h][2] += q * e2; acc[h][3] += q * e3;
                }
            }
            #pragma unroll
            for (int h = 0; h < 4; h++) {
                float inv = 1.f / (den[h] + 1e-16f);
                float* o = sA + (size_t)(h * 32 + slot) * SA_STR;
                o[lane]      = acc[h][0] * inv;  o[lane + 32] = acc[h][1] * inv;
                o[lane + 64] = acc[h][2] * inv;  o[lane + 96] = acc[h][3] * inv;
            }
            if (lane == 0) { g_need1[d] = 0; g_deg1[d] = 0; g_fc1[d] = 0; }
        }
    }
    __syncthreads();

    // ---- GEMM phase (tf32 mma): warp w -> head h = w>>1, slots (w&1)*16.. ----
    const int h     = w >> 1;
    const int mhalf = (w & 1) * 16;
    const int g     = lane >> 2;       // quad group
    const int t     = lane & 3;        // quad col
    float acc[4][4];                   // [ntile][c0..c3]
    #pragma unroll
    for (int i = 0; i < 4; i++)
        #pragma unroll
        for (int j = 0; j < 4; j++) acc[i][j] = 0.f;

    const int brow = tid >> 4;
    const int bcol = (tid & 15) * 8;
    const float* sAh = sA + (size_t)h * 32 * SA_STR;
    for (int kk = 0; kk < DIM; kk += 16) {
        *(float4*)&sB[brow * SB_STR + bcol]     = *(const float4*)(W1 + (size_t)(kk + brow) * DIM + bcol);
        *(float4*)&sB[brow * SB_STR + bcol + 4] = *(const float4*)(W1 + (size_t)(kk + brow) * DIM + bcol + 4);
        __syncthreads();
        #pragma unroll
        for (int k8 = 0; k8 < 16; k8 += 8) {
            uint32_t a0 = __float_as_uint(sAh[(mhalf + g)     * SA_STR + kk + k8 + t]);
            uint32_t a1 = __float_as_uint(sAh[(mhalf + g + 8) * SA_STR + kk + k8 + t]);
            uint32_t a2 = __float_as_uint(sAh[(mhalf + g)     * SA_STR + kk + k8 + t + 4]);
            uint32_t a3 = __float_as_uint(sAh[(mhalf + g + 8) * SA_STR + kk + k8 + t + 4]);
            #pragma unroll
            for (int nt = 0; nt < 4; nt++) {
                int n = h * 32 + nt * 8 + g;
                uint32_t b0 = __float_as_uint(sB[(k8 + t)     * SB_STR + n]);
                uint32_t b1 = __float_as_uint(sB[(k8 + t + 4) * SB_STR + n]);
                mma8(acc[nt][0], acc[nt][1], acc[nt][2], acc[nt][3],
                     a0, a1, a2, a3, b0, b1);
            }
        }
        __syncthreads();
    }

    // epilogue: c0,c1 -> slot mhalf+g, cols 2t,2t+1; c2,c3 -> slot mhalf+g+8
    #pragma unroll
    for (int nt = 0; nt < 4; nt++) {
        int col = h * 32 + nt * 8 + 2 * t;
        float b0 = bias1[col], b1 = bias1[col + 1];
        int s0 = mhalf + g, s1 = mhalf + g + 8;
        if (row0 + s0 < cnt) {
            float* o = g_h1 + (size_t)sNode[s0] * DIM + col;
            *(float2*)o = make_float2(eluf(acc[nt][0] + b0), eluf(acc[nt][1] + b1));
        }
        if (row0 + s1 < cnt) {
            float* o = g_h1 + (size_t)sNode[s1] * DIM + col;
            *(float2*)o = make_float2(eluf(acc[nt][2] + b0), eluf(acc[nt][3] + b1));
        }
    }
}

// ---------------- 3: fused layer-2 gather + TF32-mma GEMM --------------------
// block = 128 need2 nodes. sA[128][SA_STR], sB[16][SB_STR].
#define SM2_SA   (128 * SA_STR)
#define SM2_SB   (16 * SB_STR)
#define SMEM2    ((SM2_SA + SM2_SB) * 4 + 128 * 4)
__global__ __launch_bounds__(256)
void fused2_k(const float* __restrict__ W2, const float* __restrict__ bias2)
{
    extern __shared__ float smem[];
    float* sA = smem;
    float* sB = smem + SM2_SA;
    int*   sNode = (int*)(smem + SM2_SA + SM2_SB);

    const int cnt  = g_cnt2;
    const int row0 = blockIdx.x * 128;
    if (row0 >= cnt) return;
    const int tid  = threadIdx.x;
    const int w    = tid >> 5, lane = tid & 31;

    if (tid < 128) sNode[tid] = (row0 + tid < cnt) ? g_list2[row0 + tid] : -1;
    __syncthreads();

    // ---- gather phase: warp w -> nodes w*16 .. w*16+15 ----
    {
        float wr[4], wdr[4];
        #pragma unroll
        for (int j = 0; j < 4; j++) {
            wr[j]  = g_ws2[lane + 32 * j];
            wdr[j] = g_wd2[lane + 32 * j];
        }
        for (int j16 = 0; j16 < 16; j16++) {
            int slot = w * 16 + j16;
            int d = sNode[slot];
            float* o = sA + (size_t)slot * SA_STR;
            if (d < 0) {
                o[lane] = 0.f; o[lane + 32] = 0.f;
                o[lane + 64] = 0.f; o[lane + 96] = 0.f;
                continue;
            }
            const float* hd = g_h1 + (size_t)d * DIM;
            float v0 = hd[lane];      float v1 = hd[lane + 32];
            float v2 = hd[lane + 64]; float v3 = hd[lane + 96];
            float ad  = wsum(v0 * wr[0] + v1 * wr[1] + v2 * wr[2] + v3 * wr[3]);
            float b2d = wsum(v0 * wdr[0] + v1 * wdr[1] + v2 * wdr[2] + v3 * wdr[3]);
            float ww = expf(lrelu(ad + b2d));
            float den = ww;
            float a0 = ww * v0, a1 = ww * v1, a2 = ww * v2, a3 = ww * v3;
            int base = g_base2[d], deg = g_deg2[d];
            for (int k = base; k < base + deg; k++) {
                int s = g_csr2[k];
                const float* hs = g_h1 + (size_t)s * DIM;
                float e0 = hs[lane];      float e1 = hs[lane + 32];
                float e2 = hs[lane + 64]; float e3 = hs[lane + 96];
                float as = wsum(e0 * wr[0] + e1 * wr[1] + e2 * wr[2] + e3 * wr[3]);
                float q = expf(lrelu(as + b2d));
                den += q;
                a0 += q * e0; a1 += q * e1; a2 += q * e2; a3 += q * e3;
            }
            float inv = 1.f / (den + 1e-16f);
            o[lane]      = a0 * inv;  o[lane + 32] = a1 * inv;
            o[lane + 64] = a2 * inv;  o[lane + 96] = a3 * inv;
            if (lane == 0) { g_need2[d] = 0; g_deg2[d] = 0; g_fc2[d] = 0; }
        }
    }
    __syncthreads();

    // ---- GEMM phase (tf32 mma): warp w -> rows w*16..w*16+15, all 128 cols ---
    const int g = lane >> 2;
    const int t = lane & 3;
    const int mrow = w * 16;
    float acc[16][4];
    #pragma unroll
    for (int i = 0; i < 16; i++)
        #pragma unroll
        for (int j = 0; j < 4; j++) acc[i][j] = 0.f;

    const int brow = tid >> 4;
    const int bcol = (tid & 15) * 8;
    for (int kk = 0; kk < DIM; kk += 16) {
        *(float4*)&sB[brow * SB_STR + bcol]     = *(const float4*)(W2 + (size_t)(kk + brow) * DIM + bcol);
        *(float4*)&sB[brow * SB_STR + bcol + 4] = *(const float4*)(W2 + (size_t)(kk + brow) * DIM + bcol + 4);
        __syncthreads();
        #pragma unroll
        for (int k8 = 0; k8 < 16; k8 += 8) {
            uint32_t a0 = __float_as_uint(sA[(mrow + g)     * SA_STR + kk + k8 + t]);
            uint32_t a1 = __float_as_uint(sA[(mrow + g + 8) * SA_STR + kk + k8 + t]);
            uint32_t a2 = __float_as_uint(sA[(mrow + g)     * SA_STR + kk + k8 + t + 4]);
            uint32_t a3 = __float_as_uint(sA[(mrow + g + 8) * SA_STR + kk + k8 + t + 4]);
            #pragma unroll
            for (int nt = 0; nt < 16; nt++) {
                int n = nt * 8 + g;
                uint32_t b0 = __float_as_uint(sB[(k8 + t)     * SB_STR + n]);
                uint32_t b1 = __float_as_uint(sB[(k8 + t + 4) * SB_STR + n]);
                mma8(acc[nt][0], acc[nt][1], acc[nt][2], acc[nt][3],
                     a0, a1, a2, a3, b0, b1);
            }
        }
        __syncthreads();
    }

    #pragma unroll
    for (int nt = 0; nt < 16; nt++) {
        int col = nt * 8 + 2 * t;
        float b0 = bias2[col], b1 = bias2[col + 1];
        int s0 = mrow + g, s1 = mrow + g + 8;
        if (row0 + s0 < cnt) {
            float* o = g_h1 + (size_t)sNode[s0] * DIM + col;   // h2 aliases h1
            *(float2*)o = make_float2(eluf(acc[nt][0] + b0), eluf(acc[nt][1] + b1));
        }
        if (row0 + s1 < cnt) {
            float* o = g_h1 + (size_t)sNode[s1] * DIM + col;
            *(float2*)o = make_float2(eluf(acc[nt][2] + b0), eluf(acc[nt][3] + b1));
        }
    }
}

// ---------------- 4: final dot + sigmoid -------------------------------------
__global__ __launch_bounds__(256)
void final_k(const int* __restrict__ uidx, const int* __restrict__ iidx,
             float* __restrict__ res)
{
    int b    = (blockIdx.x * blockDim.x + threadIdx.x) >> 5;
    int lane = threadIdx.x & 31;
    if (b >= BATCH) return;
    const float* ru = g_h1 + (size_t)uidx[b] * DIM;
    const float* rv = g_h1 + (size_t)(iidx[b] + NUM_USERS) * DIM;
    float dot = ru[lane]      * rv[lane]
              + ru[lane + 32] * rv[lane + 32]
              + ru[lane + 64] * rv[lane + 64]
              + ru[lane + 96] * rv[lane + 96];
    dot = wsum(dot);
    if (lane == 0) res[b] = 1.f / (1.f + expf(-dot));
}

// ---------------- launch -----------------------------------------------------
extern "C" void kernel_launch(void* const* d_in, const int* in_sizes, int n_in,
                              void* d_out, int out_size)
{
    const int*   uidx  = (const int*)  d_in[0];
    const int*   iidx  = (const int*)  d_in[1];
    const int*   ei    = (const int*)  d_in[2];
    const float* userT = (const float*)d_in[3];
    const float* itemT = (const float*)d_in[4];
    const float* W1    = (const float*)d_in[5];
    const float* attS1 = (const float*)d_in[6];
    const float* attD1 = (const float*)d_in[7];
    const float* bias1 = (const float*)d_in[8];
    const float* W2    = (const float*)d_in[9];
    const float* attS2 = (const float*)d_in[10];
    const float* attD2 = (const float*)d_in[11];
    const float* bias2 = (const float*)d_in[12];
    float* res = (float*)d_out;

    cudaFuncSetAttribute(fused1_k, cudaFuncAttributeMaxDynamicSharedMemorySize, SMEM1);
    cudaFuncSetAttribute(fused2_k, cudaFuncAttributeMaxDynamicSharedMemorySize, SMEM2);

    megaprep_k<<<NBLK, 256>>>(W1, attS1, attD1, W2, attS2, attD2, uidx, iidx, ei);
    fused1_k  <<<(MAXL1 + 31) / 32,   256, SMEM1>>>(userT, itemT, W1, bias1);
    fused2_k  <<<(MAXL2 + 127) / 128, 256, SMEM2>>>(W2, bias2);
    final_k   <<<(BATCH + 7) / 8, 256>>>(uidx, iidx, res);
}